// round 1
// baseline (speedup 1.0000x reference)
#include <cuda_runtime.h>
#include <cuda_bf16.h>

// PowerSpectrum: out[n, l*512 + q*16 + p] = cg[l] * sum_m x_nu[l,n,m,q] * x_1[l,n,m,p]
// L=4, M=7, F_NU=32, F_1=16, N derived from in_sizes.

#define PS_L  4
#define PS_M  7
#define PS_FN 32
#define PS_FP 16
#define OUT_PER_N (PS_L * PS_FN * PS_FP)   // 2048

__global__ __launch_bounds__(128)
void ps_kernel(const float* __restrict__ x_nu,
               const float* __restrict__ x_1,
               float* __restrict__ out,
               int N)
{
    // x_1 tile for this n: [L=4][M*FP=112] floats = 448 floats = 1792 B
    __shared__ float x1_sh[PS_L * PS_M * PS_FP];

    const int n = blockIdx.x;
    const int t = threadIdx.x;

    // Cooperative load of x_1 (112 float4s, coalesced per l-chunk).
    // Source chunk for l is contiguous: x_1 + (l*N + n) * 112
    if (t < (PS_L * PS_M * PS_FP) / 4) {           // t in [0,112)
        const int l   = t / ((PS_M * PS_FP) / 4);  // /28
        const int idx = t % ((PS_M * PS_FP) / 4);
        const float4* src = reinterpret_cast<const float4*>(
            x_1 + ((size_t)l * N + n) * (PS_M * PS_FP));
        reinterpret_cast<float4*>(x1_sh)[t] = src[idx];
    }
    __syncthreads();

    const int l = t >> 5;     // 0..3
    const int q = t & 31;     // 0..31

    // Front-batched x_nu loads: 7 coalesced LDG.32 (consecutive lanes -> consecutive q)
    const float* xn = x_nu + ((size_t)l * N + n) * (PS_M * PS_FN) + q;
    float a[PS_M];
#pragma unroll
    for (int m = 0; m < PS_M; m++) a[m] = xn[m * PS_FN];

    float4 acc0 = make_float4(0.f, 0.f, 0.f, 0.f);
    float4 acc1 = acc0, acc2 = acc0, acc3 = acc0;

    const float4* b = reinterpret_cast<const float4*>(x1_sh + l * (PS_M * PS_FP));
#pragma unroll
    for (int m = 0; m < PS_M; m++) {
        const float am = a[m];
        float4 b0 = b[m * 4 + 0];
        float4 b1 = b[m * 4 + 1];
        float4 b2 = b[m * 4 + 2];
        float4 b3 = b[m * 4 + 3];
        acc0.x = fmaf(am, b0.x, acc0.x);
        acc0.y = fmaf(am, b0.y, acc0.y);
        acc0.z = fmaf(am, b0.z, acc0.z);
        acc0.w = fmaf(am, b0.w, acc0.w);
        acc1.x = fmaf(am, b1.x, acc1.x);
        acc1.y = fmaf(am, b1.y, acc1.y);
        acc1.z = fmaf(am, b1.z, acc1.z);
        acc1.w = fmaf(am, b1.w, acc1.w);
        acc2.x = fmaf(am, b2.x, acc2.x);
        acc2.y = fmaf(am, b2.y, acc2.y);
        acc2.z = fmaf(am, b2.z, acc2.z);
        acc2.w = fmaf(am, b2.w, acc2.w);
        acc3.x = fmaf(am, b3.x, acc3.x);
        acc3.y = fmaf(am, b3.y, acc3.y);
        acc3.z = fmaf(am, b3.z, acc3.z);
        acc3.w = fmaf(am, b3.w, acc3.w);
    }

    // cg = 1/sqrt(2l+1), exact-enough fp32 constants
    const float cgs[PS_L] = {1.0f, 0.57735026918962576f,
                             0.44721359549995794f, 0.37796447300922722f};
    const float cg = cgs[l];

    acc0.x *= cg; acc0.y *= cg; acc0.z *= cg; acc0.w *= cg;
    acc1.x *= cg; acc1.y *= cg; acc1.z *= cg; acc1.w *= cg;
    acc2.x *= cg; acc2.y *= cg; acc2.z *= cg; acc2.w *= cg;
    acc3.x *= cg; acc3.y *= cg; acc3.z *= cg; acc3.w *= cg;

    // Output: thread t owns 16 consecutive floats out[n, t*16 .. t*16+15]
    float4* o = reinterpret_cast<float4*>(out + (size_t)n * OUT_PER_N + t * PS_FP);
    o[0] = acc0;
    o[1] = acc1;
    o[2] = acc2;
    o[3] = acc3;
}

extern "C" void kernel_launch(void* const* d_in, const int* in_sizes, int n_in,
                              void* d_out, int out_size)
{
    const float* x_nu = (const float*)d_in[0];
    const float* x_1  = (const float*)d_in[1];
    float* out = (float*)d_out;

    const int N = in_sizes[0] / (PS_L * PS_M * PS_FN);

    ps_kernel<<<N, 128>>>(x_nu, x_1, out, N);
}

// round 2
// speedup vs baseline: 1.1156x; 1.1156x over previous
#include <cuda_runtime.h>
#include <cuda_bf16.h>

// PowerSpectrum: out[n, l*512 + q*16 + p] = cg[l] * sum_m x_nu[l,n,m,q] * x_1[l,n,m,p]
// L=4, M=7, F_NU=32, F_1=16.
//
// Round-2 design: warp <-> (n, l). Lane j owns p-quad (j&3)*4 and q = (j>>2)+8k (k=0..3).
// This makes every warp store instruction exactly 512B contiguous (minimal store
// wavefronts), which was the dominant L1 cost in round 1. Both inputs are staged
// in shared and read back with conflict-free single-phase LDS.

#define PS_L  4
#define PS_M  7
#define PS_FN 32
#define PS_FP 16
#define OUT_PER_N (PS_L * PS_FN * PS_FP)     // 2048
#define XNU_PER_LN (PS_M * PS_FN)            // 224 floats (56 float4)
#define X1_PER_LN  (PS_M * PS_FP)            // 112 floats (28 float4)

__global__ __launch_bounds__(128)
void ps_kernel(const float* __restrict__ x_nu,
               const float* __restrict__ x_1,
               float* __restrict__ out,
               int N)
{
    __shared__ float xns[PS_L * XNU_PER_LN];   // 896 floats
    __shared__ float x1s[PS_L * X1_PER_LN];    // 448 floats

    const int n = blockIdx.x;
    const int t = threadIdx.x;

    // ---- Cooperative load of both tiles for this n (336 float4 total) ----
    // x_nu chunk for l is contiguous at x_nu + (l*N + n)*224 (56 float4)
    // x_1  chunk for l is contiguous at x_1  + (l*N + n)*112 (28 float4)
#pragma unroll
    for (int f = t; f < 336; f += 128) {
        if (f < 224) {
            const int l   = f / 56;
            const int idx = f % 56;
            const float4* src = reinterpret_cast<const float4*>(x_nu) +
                                ((size_t)l * N + n) * 56 + idx;
            reinterpret_cast<float4*>(xns)[l * 56 + idx] = *src;
        } else {
            const int g   = f - 224;
            const int l   = g / 28;
            const int idx = g % 28;
            const float4* src = reinterpret_cast<const float4*>(x_1) +
                                ((size_t)l * N + n) * 28 + idx;
            reinterpret_cast<float4*>(x1s)[l * 28 + idx] = *src;
        }
    }
    __syncthreads();

    const int l  = t >> 5;      // warp -> l
    const int j  = t & 31;      // lane
    const int qb = j >> 2;      // q base 0..7 (q = qb + 8k)
    const int pq = j & 3;       // p-quad index (p = pq*4 .. pq*4+3)

    const float*  an = xns + l * XNU_PER_LN;                       // [m*32 + q]
    const float4* bp = reinterpret_cast<const float4*>(x1s) + l * 28 + pq;  // [m*4 + pq]

    float4 acc0 = make_float4(0.f, 0.f, 0.f, 0.f);
    float4 acc1 = acc0, acc2 = acc0, acc3 = acc0;

#pragma unroll
    for (int m = 0; m < PS_M; m++) {
        // b: 1 LDS.128, 4 distinct consecutive float4 across warp (conflict-free)
        const float4 b = bp[m * 4];
        // a: 4 LDS.32, 8 consecutive distinct words across warp (conflict-free, 4-way bcast)
        const float a0 = an[m * PS_FN + qb +  0];
        const float a1 = an[m * PS_FN + qb +  8];
        const float a2 = an[m * PS_FN + qb + 16];
        const float a3 = an[m * PS_FN + qb + 24];

        acc0.x = fmaf(a0, b.x, acc0.x);
        acc0.y = fmaf(a0, b.y, acc0.y);
        acc0.z = fmaf(a0, b.z, acc0.z);
        acc0.w = fmaf(a0, b.w, acc0.w);
        acc1.x = fmaf(a1, b.x, acc1.x);
        acc1.y = fmaf(a1, b.y, acc1.y);
        acc1.z = fmaf(a1, b.z, acc1.z);
        acc1.w = fmaf(a1, b.w, acc1.w);
        acc2.x = fmaf(a2, b.x, acc2.x);
        acc2.y = fmaf(a2, b.y, acc2.y);
        acc2.z = fmaf(a2, b.z, acc2.z);
        acc2.w = fmaf(a2, b.w, acc2.w);
        acc3.x = fmaf(a3, b.x, acc3.x);
        acc3.y = fmaf(a3, b.y, acc3.y);
        acc3.z = fmaf(a3, b.z, acc3.z);
        acc3.w = fmaf(a3, b.w, acc3.w);
    }

    const float cgs[PS_L] = {1.0f, 0.57735026918962576f,
                             0.44721359549995794f, 0.37796447300922722f};
    const float cg = cgs[l];

    acc0.x *= cg; acc0.y *= cg; acc0.z *= cg; acc0.w *= cg;
    acc1.x *= cg; acc1.y *= cg; acc1.z *= cg; acc1.w *= cg;
    acc2.x *= cg; acc2.y *= cg; acc2.z *= cg; acc2.w *= cg;
    acc3.x *= cg; acc3.y *= cg; acc3.z *= cg; acc3.w *= cg;

    // acc[k] covers (q = qb + 8k, p = pq*4..pq*4+3):
    // float4 output index = q*4 + pq = j + 32k  -> fully coalesced 512B per STG
    float4* o = reinterpret_cast<float4*>(out + (size_t)n * OUT_PER_N + l * (PS_FN * PS_FP));
    o[j +  0] = acc0;
    o[j + 32] = acc1;
    o[j + 64] = acc2;
    o[j + 96] = acc3;
}

extern "C" void kernel_launch(void* const* d_in, const int* in_sizes, int n_in,
                              void* d_out, int out_size)
{
    const float* x_nu = (const float*)d_in[0];
    const float* x_1  = (const float*)d_in[1];
    float* out = (float*)d_out;

    const int N = in_sizes[0] / (PS_L * PS_M * PS_FN);

    ps_kernel<<<N, 128>>>(x_nu, x_1, out, N);
}